// round 4
// baseline (speedup 1.0000x reference)
#include <cuda_runtime.h>
#include <cuda_bf16.h>

#define NLEV 4
#define MAXS 792
#define NTHREADS 256

// R3: identical to R0 design; previous round failed on infra (container), not kernel.
// params table: NLEV*MAXS float2 = 6336 entries = 25344 bytes in smem.
__global__ __launch_bounds__(NTHREADS) void heal_encoding_kernel(
    const float2* __restrict__ params2,      // [NLEV*MAXS] as float2
    const float2* __restrict__ pixel_ll,     // [NLEV, B] as float2
    const float2* __restrict__ neigh_ll,     // [NLEV, 8, B] as float2
    const int*    __restrict__ pixel_idx,    // [NLEV, B]
    const int*    __restrict__ neigh_idx,    // [NLEV, 8, B]
    float*        __restrict__ out,          // [B, 8]  out[b, 4f+l]
    int B)
{
    __shared__ float2 sp[NLEV * MAXS];
    for (int i = threadIdx.x; i < NLEV * MAXS; i += NTHREADS)
        sp[i] = params2[i];
    __syncthreads();

    int b = blockIdx.x * NTHREADS + threadIdx.x;
    if (b >= B) return;

    float acc0[NLEV];   // f = 0 per level
    float acc1[NLEV];   // f = 1 per level

#pragma unroll
    for (int l = 0; l < NLEV; l++) {
        const int   p  = pixel_idx[l * B + b];
        const float2 pl = pixel_ll[l * B + b];
        const float2 r  = sp[l * MAXS + p];   // residual (my_reps)
        float s0 = r.x;
        float s1 = r.y;
#pragma unroll
        for (int j = 0; j < 8; j++) {
            const int    n  = neigh_idx[(l * 8 + j) * B + b];
            const float2 nl = neigh_ll[(l * 8 + j) * B + b];
            if (n >= 0) {
                const float dx = nl.x - pl.x;
                const float dy = nl.y - pl.y;
                const float w  = rsqrtf(fmaf(dx, dx, dy * dy));  // 1/d
                const float2 v = sp[l * MAXS + n];
                s0 = fmaf(w, v.x, s0);
                s1 = fmaf(w, v.y, s1);
            }
        }
        acc0[l] = s0;
        acc1[l] = s1;
    }

    // out[b, 4f + l]: 8 contiguous floats per sample -> two float4 stores
    float4 o0 = make_float4(acc0[0], acc0[1], acc0[2], acc0[3]);
    float4 o1 = make_float4(acc1[0], acc1[1], acc1[2], acc1[3]);
    float4* op = reinterpret_cast<float4*>(out + (size_t)b * 8);
    op[0] = o0;
    op[1] = o1;
}

extern "C" void kernel_launch(void* const* d_in, const int* in_sizes, int n_in,
                              void* d_out, int out_size)
{
    // metadata order: params, pixel_latlon, neigh_latlon, pixel_index, neigh_index
    const float2* params2   = (const float2*)d_in[0];
    const float2* pixel_ll  = (const float2*)d_in[1];
    const float2* neigh_ll  = (const float2*)d_in[2];
    const int*    pixel_idx = (const int*)d_in[3];
    const int*    neigh_idx = (const int*)d_in[4];
    float*        out       = (float*)d_out;

    const int B = in_sizes[3] / NLEV;   // pixel_index has NLEV*B elements

    const int grid = (B + NTHREADS - 1) / NTHREADS;
    heal_encoding_kernel<<<grid, NTHREADS>>>(
        params2, pixel_ll, neigh_ll, pixel_idx, neigh_idx, out, B);
}